// round 1
// baseline (speedup 1.0000x reference)
#include <cuda_runtime.h>
#include <math.h>

#define DD 128
#define NMAX 100000
#define NPART 250

// Scratch (allocation-free: __device__ globals)
__device__ float g_h[(size_t)NMAX * DD];     // normalized features
__device__ float g_agg[(size_t)NMAX * DD];   // neighbor sum -> mean
__device__ float g_deg[NMAX];
__device__ float g_psum[NPART * DD];
__device__ float g_psq[NPART * DD];
__device__ float g_scale[DD];
__device__ float g_shift[DD];

__device__ __forceinline__ float gelu_exact(float x) {
    return 0.5f * x * (1.0f + erff(x * 0.70710678118654752440f));
}

// ---------------- Stage 1: column-wise sum / sumsq partials ----------------
__global__ void bn_partial(const float* __restrict__ f, int n, int rpb) {
    int d = threadIdx.x;              // 128 threads, one per feature dim
    int r0 = blockIdx.x * rpb;
    int r1 = min(r0 + rpb, n);
    float s = 0.f, sq = 0.f;
    for (int r = r0; r < r1; ++r) {
        float v = f[(size_t)r * DD + d];
        s += v;
        sq += v * v;
    }
    g_psum[blockIdx.x * DD + d] = s;
    g_psq[blockIdx.x * DD + d]  = sq;
}

// ---------------- Stage 2: finalize mean/var -> scale/shift ----------------
__global__ void bn_finalize(const float* __restrict__ gamma,
                            const float* __restrict__ beta, int n) {
    int d = threadIdx.x;
    float s = 0.f, sq = 0.f;
    for (int b = 0; b < NPART; ++b) {
        s  += g_psum[b * DD + d];
        sq += g_psq[b * DD + d];
    }
    float inv_n = 1.0f / (float)n;
    float mean = s * inv_n;
    float var  = sq * inv_n - mean * mean;   // biased variance
    float rstd = rsqrtf(var + 1e-5f);
    float sc = gamma[d] * rstd;
    g_scale[d] = sc;
    g_shift[d] = beta[d] - mean * sc;
}

// ---------------- Stage 3: normalize + zero agg/deg (fused) ----------------
__global__ void normalize_zero(const float* __restrict__ f, int n) {
    int t = blockIdx.x * blockDim.x + threadIdx.x;
    int slots = n * (DD / 4);
    if (t < slots) {
        float4 v = ((const float4*)f)[t];
        int d4 = t & 31;                       // 32 float4 per row
        float4 sc = ((const float4*)g_scale)[d4];
        float4 sh = ((const float4*)g_shift)[d4];
        float4 h;
        h.x = v.x * sc.x + sh.x;
        h.y = v.y * sc.y + sh.y;
        h.z = v.z * sc.z + sh.z;
        h.w = v.w * sc.w + sh.w;
        ((float4*)g_h)[t] = h;
        ((float4*)g_agg)[t] = make_float4(0.f, 0.f, 0.f, 0.f);
    }
    int dslots = (n + 3) >> 2;
    if (t < dslots) {
        int base = t * 4;
        if (base + 3 < n) {
            ((float4*)g_deg)[t] = make_float4(0.f, 0.f, 0.f, 0.f);
        } else {
            for (int i = base; i < n; ++i) g_deg[i] = 0.f;
        }
    }
}

// ---------------- Stage 4: edge gather + atomic scatter ----------------
__global__ void scatter_edges(const int* __restrict__ src,
                              const int* __restrict__ dst, int e) {
    int gw = (blockIdx.x * blockDim.x + threadIdx.x) >> 5;  // one warp per edge
    int lane = threadIdx.x & 31;
    if (gw >= e) return;
    int s = src[gw];
    int d = dst[gw];
    float4 v = ((const float4*)(g_h + (size_t)s * DD))[lane];
    float* ap = g_agg + (size_t)d * DD + lane * 4;
    atomicAdd(ap + 0, v.x);
    atomicAdd(ap + 1, v.y);
    atomicAdd(ap + 2, v.z);
    atomicAdd(ap + 3, v.w);
    if (lane == 0) atomicAdd(&g_deg[d], 1.0f);
}

// ---------------- Stage 5: agg -> mean (divide by deg) ----------------
__global__ void hn_div(int n) {
    int t = blockIdx.x * blockDim.x + threadIdx.x;
    int slots = n * (DD / 4);
    if (t >= slots) return;
    int node = t >> 5;
    float inv = 1.0f / fmaxf(g_deg[node], 1.0f);
    float4 v = ((float4*)g_agg)[t];
    v.x *= inv; v.y *= inv; v.z *= inv; v.w *= inv;
    ((float4*)g_agg)[t] = v;
}

// ---------------- Stage 6: fused GEMM + bias + skip + GELU ----------------
// conv = [h | hn] @ [W_self ; W_neigh]  (M x 256) @ (256 x 128)
// BM=128, BN=128, BK=16, 256 threads, 8x8 microtile (split columns for
// conflict-free LDS.128 on the B tile).
__global__ __launch_bounds__(256) void gemm_gelu(
    const float* __restrict__ Wself, const float* __restrict__ Wneigh,
    const float* __restrict__ bias, float* __restrict__ out, int n)
{
    __shared__ float As[16][128];   // [k][row]
    __shared__ float Bs[16][128];   // [k][col]

    int tid = threadIdx.x;
    int tx = tid & 15;              // column group 0..15
    int ty = tid >> 4;              // row group 0..15
    int rowBase = blockIdx.x * 128;

    float acc[8][8];
    #pragma unroll
    for (int i = 0; i < 8; ++i)
        #pragma unroll
        for (int j = 0; j < 8; ++j) acc[i][j] = 0.f;

    for (int k0 = 0; k0 < 256; k0 += 16) {
        const float* Asrc = (k0 < 128) ? (g_h + k0) : (g_agg + (k0 - 128));
        const float* Bsrc = (k0 < 128) ? (Wself + (size_t)k0 * 128)
                                       : (Wneigh + (size_t)(k0 - 128) * 128);
        // Load A tile: 512 float4 slots (row = s>>2, kq = s&3), stored transposed
        #pragma unroll
        for (int r = 0; r < 2; ++r) {
            int s = tid + r * 256;
            int row = s >> 2, kq = s & 3;
            int grow = rowBase + row;
            float4 v = make_float4(0.f, 0.f, 0.f, 0.f);
            if (grow < n) v = *(const float4*)(Asrc + (size_t)grow * 128 + kq * 4);
            As[kq * 4 + 0][row] = v.x;
            As[kq * 4 + 1][row] = v.y;
            As[kq * 4 + 2][row] = v.z;
            As[kq * 4 + 3][row] = v.w;
        }
        // Load B tile: k = s>>5, n4 = s&31, contiguous in n
        #pragma unroll
        for (int r = 0; r < 2; ++r) {
            int s = tid + r * 256;
            int kk = s >> 5, n4 = s & 31;
            float4 v = *(const float4*)(Bsrc + kk * 128 + n4 * 4);
            *(float4*)&Bs[kk][n4 * 4] = v;
        }
        __syncthreads();

        #pragma unroll
        for (int k = 0; k < 16; ++k) {
            float a[8], b[8];
            *(float4*)&a[0] = *(const float4*)&As[k][ty * 8];
            *(float4*)&a[4] = *(const float4*)&As[k][ty * 8 + 4];
            *(float4*)&b[0] = *(const float4*)&Bs[k][tx * 4];        // cols tx*4..+3
            *(float4*)&b[4] = *(const float4*)&Bs[k][64 + tx * 4];   // cols 64+tx*4..+3
            #pragma unroll
            for (int i = 0; i < 8; ++i)
                #pragma unroll
                for (int j = 0; j < 8; ++j)
                    acc[i][j] += a[i] * b[j];
        }
        __syncthreads();
    }

    float4 b0 = ((const float4*)bias)[tx];
    float4 b1 = ((const float4*)bias)[16 + tx];

    #pragma unroll
    for (int i = 0; i < 8; ++i) {
        int row = rowBase + ty * 8 + i;
        if (row >= n) break;
        const float* hrow = g_h + (size_t)row * 128;
        float4 h0 = *(const float4*)(hrow + tx * 4);
        float4 h1 = *(const float4*)(hrow + 64 + tx * 4);
        float4 o0, o1;
        o0.x = gelu_exact(acc[i][0] + b0.x + h0.x);
        o0.y = gelu_exact(acc[i][1] + b0.y + h0.y);
        o0.z = gelu_exact(acc[i][2] + b0.z + h0.z);
        o0.w = gelu_exact(acc[i][3] + b0.w + h0.w);
        o1.x = gelu_exact(acc[i][4] + b1.x + h1.x);
        o1.y = gelu_exact(acc[i][5] + b1.y + h1.y);
        o1.z = gelu_exact(acc[i][6] + b1.z + h1.z);
        o1.w = gelu_exact(acc[i][7] + b1.w + h1.w);
        *(float4*)(out + (size_t)row * 128 + tx * 4) = o0;
        *(float4*)(out + (size_t)row * 128 + 64 + tx * 4) = o1;
    }
}

extern "C" void kernel_launch(void* const* d_in, const int* in_sizes, int n_in,
                              void* d_out, int out_size) {
    const float* features = (const float*)d_in[0];
    const int*   src      = (const int*)d_in[1];
    const int*   dst      = (const int*)d_in[2];
    const float* gamma    = (const float*)d_in[3];
    const float* beta     = (const float*)d_in[4];
    const float* Wself    = (const float*)d_in[5];
    const float* Wneigh   = (const float*)d_in[6];
    const float* bias     = (const float*)d_in[7];
    float* out = (float*)d_out;

    int n = in_sizes[0] / DD;
    int e = in_sizes[1];
    int rpb = (n + NPART - 1) / NPART;

    bn_partial<<<NPART, DD>>>(features, n, rpb);
    bn_finalize<<<1, DD>>>(gamma, beta, n);

    int slots = n * (DD / 4);
    int nzblocks = (slots + 255) / 256;
    normalize_zero<<<nzblocks, 256>>>(features, n);

    int sthreads = e * 32;
    scatter_edges<<<(sthreads + 255) / 256, 256>>>(src, dst, e);

    hn_div<<<nzblocks, 256>>>(n);

    gemm_gelu<<<(n + 127) / 128, 256>>>(Wself, Wneigh, bias, out, n);
}

// round 3
// speedup vs baseline: 1.4243x; 1.4243x over previous
#include <cuda_runtime.h>
#include <math.h>

#define DD 128
#define NMAX 100000
#define NPART 250

// Scratch (allocation-free: __device__ globals)
__device__ float g_h[(size_t)NMAX * DD];     // normalized features
__device__ float g_agg[(size_t)NMAX * DD];   // neighbor sum
__device__ float g_deg[NMAX];
__device__ float g_psum[NPART * DD];
__device__ float g_psq[NPART * DD];
__device__ float g_scale[DD];
__device__ float g_shift[DD];

__device__ __forceinline__ float gelu_exact(float x) {
    return 0.5f * x * (1.0f + erff(x * 0.70710678118654752440f));
}

// ---------------- Stage 1: column-wise sum / sumsq partials ----------------
__global__ void bn_partial(const float* __restrict__ f, int n, int rpb) {
    int d = threadIdx.x;              // 128 threads, one per feature dim
    int r0 = blockIdx.x * rpb;
    int r1 = min(r0 + rpb, n);
    float s = 0.f, sq = 0.f;
    for (int r = r0; r < r1; ++r) {
        float v = f[(size_t)r * DD + d];
        s += v;
        sq += v * v;
    }
    g_psum[blockIdx.x * DD + d] = s;
    g_psq[blockIdx.x * DD + d]  = sq;
}

// ---------------- Stage 2: finalize mean/var -> scale/shift ----------------
__global__ void bn_finalize(const float* __restrict__ gamma,
                            const float* __restrict__ beta, int n) {
    int d = threadIdx.x;
    float s = 0.f, sq = 0.f;
    for (int b = 0; b < NPART; ++b) {
        s  += g_psum[b * DD + d];
        sq += g_psq[b * DD + d];
    }
    float inv_n = 1.0f / (float)n;
    float mean = s * inv_n;
    float var  = sq * inv_n - mean * mean;   // biased variance
    float rstd = rsqrtf(var + 1e-5f);
    float sc = gamma[d] * rstd;
    g_scale[d] = sc;
    g_shift[d] = beta[d] - mean * sc;
}

// ---------------- Stage 3: normalize + zero agg/deg (fused) ----------------
__global__ void normalize_zero(const float* __restrict__ f, int n) {
    int t = blockIdx.x * blockDim.x + threadIdx.x;
    int slots = n * (DD / 4);
    if (t < slots) {
        float4 v = ((const float4*)f)[t];
        int d4 = t & 31;                       // 32 float4 per row
        float4 sc = ((const float4*)g_scale)[d4];
        float4 sh = ((const float4*)g_shift)[d4];
        float4 h;
        h.x = v.x * sc.x + sh.x;
        h.y = v.y * sc.y + sh.y;
        h.z = v.z * sc.z + sh.z;
        h.w = v.w * sc.w + sh.w;
        ((float4*)g_h)[t] = h;
        ((float4*)g_agg)[t] = make_float4(0.f, 0.f, 0.f, 0.f);
    }
    int dslots = (n + 3) >> 2;
    if (t < dslots) {
        int base = t * 4;
        if (base + 3 < n) {
            ((float4*)g_deg)[t] = make_float4(0.f, 0.f, 0.f, 0.f);
        } else {
            for (int i = base; i < n; ++i) g_deg[i] = 0.f;
        }
    }
}

// ---------------- Stage 4: edge gather + vector-red scatter ----------------
__global__ void scatter_edges(const int* __restrict__ src,
                              const int* __restrict__ dst, int e) {
    int gw = (blockIdx.x * blockDim.x + threadIdx.x) >> 5;  // one warp per edge
    int lane = threadIdx.x & 31;
    if (gw >= e) return;
    int s = src[gw];
    int d = dst[gw];
    float4 v = ((const float4*)(g_h + (size_t)s * DD))[lane];
    float* ap = g_agg + (size_t)d * DD + lane * 4;
    asm volatile("red.global.add.v4.f32 [%0], {%1, %2, %3, %4};"
                 :: "l"(ap), "f"(v.x), "f"(v.y), "f"(v.z), "f"(v.w)
                 : "memory");
    if (lane == 0) atomicAdd(&g_deg[d], 1.0f);
}

// ---------------- Stage 5: fused GEMM + deg-div + bias + skip + GELU -------
// conv = [h | hn] @ [W_self ; W_neigh]  (M x 256) @ (256 x 128)
// BM=128, BN=128, BK=16, 256 threads, 8x8 microtile computed as 8x4 packed
// f32x2 accumulators (fma.rn.f32x2 doubles fp32 FMA throughput on sm_103a).
__global__ __launch_bounds__(256) void gemm_gelu(
    const float* __restrict__ Wself, const float* __restrict__ Wneigh,
    const float* __restrict__ bias, float* __restrict__ out, int n)
{
    __shared__ float As[16][128];   // [k][row]
    __shared__ float Bs[16][128];   // [k][col]

    int tid = threadIdx.x;
    int tx = tid & 15;              // column group 0..15
    int ty = tid >> 4;              // row group 0..15
    int rowBase = blockIdx.x * 128;

    // Packed accumulators: acc2[i][0..1] -> cols tx*4 + {0,1},{2,3}
    //                      acc2[i][2..3] -> cols 64+tx*4 + {0,1},{2,3}
    unsigned long long acc2[8][4];
    #pragma unroll
    for (int i = 0; i < 8; ++i)
        #pragma unroll
        for (int j = 0; j < 4; ++j) acc2[i][j] = 0ull;

    for (int k0 = 0; k0 < 256; k0 += 16) {
        const float* Asrc = (k0 < 128) ? (g_h + k0) : (g_agg + (k0 - 128));
        const float* Bsrc = (k0 < 128) ? (Wself + (size_t)k0 * 128)
                                       : (Wneigh + (size_t)(k0 - 128) * 128);
        bool divDeg = (k0 >= 128);
        // Load A tile: 512 float4 slots (row = s>>2, kq = s&3), transposed.
        // Second half of K streams g_agg and applies the 1/max(deg,1) here
        // (fuses the former hn_div kernel).
        #pragma unroll
        for (int r = 0; r < 2; ++r) {
            int s = tid + r * 256;
            int row = s >> 2, kq = s & 3;
            int grow = rowBase + row;
            float4 v = make_float4(0.f, 0.f, 0.f, 0.f);
            if (grow < n) {
                v = *(const float4*)(Asrc + (size_t)grow * 128 + kq * 4);
                if (divDeg) {
                    float inv = 1.0f / fmaxf(g_deg[grow], 1.0f);
                    v.x *= inv; v.y *= inv; v.z *= inv; v.w *= inv;
                }
            }
            As[kq * 4 + 0][row] = v.x;
            As[kq * 4 + 1][row] = v.y;
            As[kq * 4 + 2][row] = v.z;
            As[kq * 4 + 3][row] = v.w;
        }
        // Load B tile: k = s>>5, n4 = s&31, contiguous in n
        #pragma unroll
        for (int r = 0; r < 2; ++r) {
            int s = tid + r * 256;
            int kk = s >> 5, n4 = s & 31;
            float4 v = *(const float4*)(Bsrc + kk * 128 + n4 * 4);
            *(float4*)&Bs[kk][n4 * 4] = v;
        }
        __syncthreads();

        #pragma unroll
        for (int k = 0; k < 16; ++k) {
            float a[8];
            *(float4*)&a[0] = *(const float4*)&As[k][ty * 8];
            *(float4*)&a[4] = *(const float4*)&As[k][ty * 8 + 4];
            // B pairs come straight out of LDS.128 as aligned b64 reg pairs
            ulonglong2 bp0 = *(const ulonglong2*)&Bs[k][tx * 4];
            ulonglong2 bp1 = *(const ulonglong2*)&Bs[k][64 + tx * 4];
            unsigned long long b2[4];
            b2[0] = bp0.x; b2[1] = bp0.y; b2[2] = bp1.x; b2[3] = bp1.y;
            #pragma unroll
            for (int i = 0; i < 8; ++i) {
                unsigned long long a2;
                asm("mov.b64 %0, {%1, %1};" : "=l"(a2) : "f"(a[i]));
                #pragma unroll
                for (int j = 0; j < 4; ++j) {
                    asm("fma.rn.f32x2 %0, %1, %2, %0;"
                        : "+l"(acc2[i][j]) : "l"(a2), "l"(b2[j]));
                }
            }
        }
        __syncthreads();
    }

    float4 b0 = ((const float4*)bias)[tx];
    float4 b1 = ((const float4*)bias)[16 + tx];

    #pragma unroll
    for (int i = 0; i < 8; ++i) {
        int row = rowBase + ty * 8 + i;
        if (row >= n) break;
        const float* hrow = g_h + (size_t)row * 128;
        float4 h0 = *(const float4*)(hrow + tx * 4);
        float4 h1 = *(const float4*)(hrow + 64 + tx * 4);
        float2 a01 = *(float2*)&acc2[i][0];
        float2 a23 = *(float2*)&acc2[i][1];
        float2 a45 = *(float2*)&acc2[i][2];
        float2 a67 = *(float2*)&acc2[i][3];
        float4 o0, o1;
        o0.x = gelu_exact(a01.x + b0.x + h0.x);
        o0.y = gelu_exact(a01.y + b0.y + h0.y);
        o0.z = gelu_exact(a23.x + b0.z + h0.z);
        o0.w = gelu_exact(a23.y + b0.w + h0.w);
        o1.x = gelu_exact(a45.x + b1.x + h1.x);
        o1.y = gelu_exact(a45.y + b1.y + h1.y);
        o1.z = gelu_exact(a67.x + b1.z + h1.z);
        o1.w = gelu_exact(a67.y + b1.w + h1.w);
        *(float4*)(out + (size_t)row * 128 + tx * 4) = o0;
        *(float4*)(out + (size_t)row * 128 + 64 + tx * 4) = o1;
    }
}

extern "C" void kernel_launch(void* const* d_in, const int* in_sizes, int n_in,
                              void* d_out, int out_size) {
    const float* features = (const float*)d_in[0];
    const int*   src      = (const int*)d_in[1];
    const int*   dst      = (const int*)d_in[2];
    const float* gamma    = (const float*)d_in[3];
    const float* beta     = (const float*)d_in[4];
    const float* Wself    = (const float*)d_in[5];
    const float* Wneigh   = (const float*)d_in[6];
    const float* bias     = (const float*)d_in[7];
    float* out = (float*)d_out;

    int n = in_sizes[0] / DD;
    int e = in_sizes[1];
    int rpb = (n + NPART - 1) / NPART;

    bn_partial<<<NPART, DD>>>(features, n, rpb);
    bn_finalize<<<1, DD>>>(gamma, beta, n);

    int slots = n * (DD / 4);
    int nzblocks = (slots + 255) / 256;
    normalize_zero<<<nzblocks, 256>>>(features, n);

    int sthreads = e * 32;
    scatter_edges<<<(sthreads + 255) / 256, 256>>>(src, dst, e);

    gemm_gelu<<<(n + 127) / 128, 256>>>(Wself, Wneigh, bias, out, n);
}

// round 6
// speedup vs baseline: 1.7220x; 1.2090x over previous
#include <cuda_runtime.h>
#include <math.h>

#define DD 128
#define NMAX 100000
#define EMAX 800000
#define NPART 250

// Scratch (allocation-free: __device__ globals)
__device__ float g_h[(size_t)NMAX * DD];     // normalized features
__device__ float g_agg[(size_t)NMAX * DD];   // neighbor MEAN
__device__ float g_psum[NPART * DD];
__device__ float g_psq[NPART * DD];
__device__ float g_scale[DD];
__device__ float g_shift[DD];

// CSR scratch
__device__ int g_cnt[NMAX];
__device__ int g_offs[NMAX + 1];
__device__ int g_curs[NMAX];
__device__ int g_part[256];
__device__ int g_csr[EMAX];

__device__ __forceinline__ float gelu_exact(float x) {
    return 0.5f * x * (1.0f + erff(x * 0.70710678118654752440f));
}

// ---------------- BN stats ----------------
__global__ void bn_partial(const float* __restrict__ f, int n, int rpb) {
    int d = threadIdx.x;
    int r0 = blockIdx.x * rpb;
    int r1 = min(r0 + rpb, n);
    float s = 0.f, sq = 0.f;
    for (int r = r0; r < r1; ++r) {
        float v = f[(size_t)r * DD + d];
        s += v;
        sq += v * v;
    }
    g_psum[blockIdx.x * DD + d] = s;
    g_psq[blockIdx.x * DD + d]  = sq;
}

__global__ void bn_finalize(const float* __restrict__ gamma,
                            const float* __restrict__ beta, int n) {
    int d = threadIdx.x;
    float s = 0.f, sq = 0.f;
    for (int b = 0; b < NPART; ++b) {
        s  += g_psum[b * DD + d];
        sq += g_psq[b * DD + d];
    }
    float inv_n = 1.0f / (float)n;
    float mean = s * inv_n;
    float var  = sq * inv_n - mean * mean;
    float rstd = rsqrtf(var + 1e-5f);
    float sc = gamma[d] * rstd;
    g_scale[d] = sc;
    g_shift[d] = beta[d] - mean * sc;
}

// ---------------- normalize (h only; no agg zeroing needed) ----------------
__global__ void normalize_h(const float* __restrict__ f, int n) {
    int t = blockIdx.x * blockDim.x + threadIdx.x;
    int slots = n * (DD / 4);
    if (t >= slots) return;
    float4 v = ((const float4*)f)[t];
    int d4 = t & 31;
    float4 sc = ((const float4*)g_scale)[d4];
    float4 sh = ((const float4*)g_shift)[d4];
    float4 h;
    h.x = v.x * sc.x + sh.x;
    h.y = v.y * sc.y + sh.y;
    h.z = v.z * sc.z + sh.z;
    h.w = v.w * sc.w + sh.w;
    ((float4*)g_h)[t] = h;
}

// ---------------- CSR build ----------------
__global__ void zero_cnt(int n) {
    int t = blockIdx.x * blockDim.x + threadIdx.x;
    if (t < n) g_cnt[t] = 0;
}

__global__ void hist(const int* __restrict__ dst, int e) {
    int t = blockIdx.x * blockDim.x + threadIdx.x;
    if (t < e) atomicAdd(&g_cnt[dst[t]], 1);
}

// scan1: per-block (512) local exclusive scan -> g_offs; block totals -> g_part
__global__ void scan1(int n) {
    __shared__ int sm[512];
    int t = threadIdx.x;
    int i = blockIdx.x * 512 + t;
    int v = (i < n) ? g_cnt[i] : 0;
    sm[t] = v;
    __syncthreads();
    #pragma unroll
    for (int d = 1; d < 512; d <<= 1) {
        int x = (t >= d) ? sm[t - d] : 0;
        __syncthreads();
        sm[t] += x;
        __syncthreads();
    }
    if (i < n) g_offs[i] = sm[t] - v;     // local exclusive
    if (t == 511) g_part[blockIdx.x] = sm[511];
}

// scan2: exclusive scan of block totals (nblk <= 256), write offs[n] = e
__global__ void scan2(int nblk, int n, int e) {
    __shared__ int sm[256];
    int t = threadIdx.x;
    int v = (t < nblk) ? g_part[t] : 0;
    sm[t] = v;
    __syncthreads();
    #pragma unroll
    for (int d = 1; d < 256; d <<= 1) {
        int x = (t >= d) ? sm[t - d] : 0;
        __syncthreads();
        sm[t] += x;
        __syncthreads();
    }
    if (t < nblk) g_part[t] = sm[t] - v;  // exclusive
    if (t == 0) g_offs[n] = e;
}

// scan3: add block offset; init cursor
__global__ void scan3(int n) {
    int i = blockIdx.x * 512 + threadIdx.x;
    if (i < n) {
        int o = g_offs[i] + g_part[blockIdx.x];
        g_offs[i] = o;
        g_curs[i] = o;
    }
}

__global__ void fill_csr(const int* __restrict__ src,
                         const int* __restrict__ dst, int e) {
    int t = blockIdx.x * blockDim.x + threadIdx.x;
    if (t >= e) return;
    int pos = atomicAdd(&g_curs[dst[t]], 1);
    g_csr[pos] = src[t];
}

// ---------------- aggregate: warp per dst node, register reduction ---------
__global__ void aggregate(int n) {
    int w = (blockIdx.x * blockDim.x + threadIdx.x) >> 5;
    int lane = threadIdx.x & 31;
    if (w >= n) return;
    int i  = g_offs[w];
    int s1 = g_offs[w + 1];
    int deg = s1 - i;
    float4 acc = make_float4(0.f, 0.f, 0.f, 0.f);
    int nexts = (i < s1) ? g_csr[i] : 0;
    while (i < s1) {
        int s = nexts;
        ++i;
        if (i < s1) nexts = g_csr[i];          // prefetch next index
        float4 v = ((const float4*)(g_h + (size_t)s * DD))[lane];
        acc.x += v.x; acc.y += v.y; acc.z += v.z; acc.w += v.w;
    }
    float inv = (deg > 0) ? (1.0f / (float)deg) : 0.0f;
    acc.x *= inv; acc.y *= inv; acc.z *= inv; acc.w *= inv;
    ((float4*)(g_agg + (size_t)w * DD))[lane] = acc;
}

// ---------------- fused GEMM + bias + skip + GELU --------------------------
// conv = [h | hn] @ [W_self ; W_neigh]  (M x 256) @ (256 x 128)
__global__ __launch_bounds__(256) void gemm_gelu(
    const float* __restrict__ Wself, const float* __restrict__ Wneigh,
    const float* __restrict__ bias, float* __restrict__ out, int n)
{
    __shared__ float As[16][128];   // [k][row]
    __shared__ float Bs[16][128];   // [k][col]

    int tid = threadIdx.x;
    int tx = tid & 15;
    int ty = tid >> 4;
    int rowBase = blockIdx.x * 128;

    unsigned long long acc2[8][4];
    #pragma unroll
    for (int i = 0; i < 8; ++i)
        #pragma unroll
        for (int j = 0; j < 4; ++j) acc2[i][j] = 0ull;

    for (int k0 = 0; k0 < 256; k0 += 16) {
        const float* Asrc = (k0 < 128) ? (g_h + k0) : (g_agg + (k0 - 128));
        const float* Bsrc = (k0 < 128) ? (Wself + (size_t)k0 * 128)
                                       : (Wneigh + (size_t)(k0 - 128) * 128);
        #pragma unroll
        for (int r = 0; r < 2; ++r) {
            int s = tid + r * 256;
            int row = s >> 2, kq = s & 3;
            int grow = rowBase + row;
            float4 v = make_float4(0.f, 0.f, 0.f, 0.f);
            if (grow < n) v = *(const float4*)(Asrc + (size_t)grow * 128 + kq * 4);
            As[kq * 4 + 0][row] = v.x;
            As[kq * 4 + 1][row] = v.y;
            As[kq * 4 + 2][row] = v.z;
            As[kq * 4 + 3][row] = v.w;
        }
        #pragma unroll
        for (int r = 0; r < 2; ++r) {
            int s = tid + r * 256;
            int kk = s >> 5, n4 = s & 31;
            float4 v = *(const float4*)(Bsrc + kk * 128 + n4 * 4);
            *(float4*)&Bs[kk][n4 * 4] = v;
        }
        __syncthreads();

        #pragma unroll
        for (int k = 0; k < 16; ++k) {
            float a[8];
            *(float4*)&a[0] = *(const float4*)&As[k][ty * 8];
            *(float4*)&a[4] = *(const float4*)&As[k][ty * 8 + 4];
            ulonglong2 bp0 = *(const ulonglong2*)&Bs[k][tx * 4];
            ulonglong2 bp1 = *(const ulonglong2*)&Bs[k][64 + tx * 4];
            unsigned long long b2[4];
            b2[0] = bp0.x; b2[1] = bp0.y; b2[2] = bp1.x; b2[3] = bp1.y;
            #pragma unroll
            for (int i = 0; i < 8; ++i) {
                unsigned long long a2;
                asm("mov.b64 %0, {%1, %1};" : "=l"(a2) : "f"(a[i]));
                #pragma unroll
                for (int j = 0; j < 4; ++j) {
                    asm("fma.rn.f32x2 %0, %1, %2, %0;"
                        : "+l"(acc2[i][j]) : "l"(a2), "l"(b2[j]));
                }
            }
        }
        __syncthreads();
    }

    float4 b0 = ((const float4*)bias)[tx];
    float4 b1 = ((const float4*)bias)[16 + tx];

    #pragma unroll
    for (int i = 0; i < 8; ++i) {
        int row = rowBase + ty * 8 + i;
        if (row >= n) break;
        const float* hrow = g_h + (size_t)row * 128;
        float4 h0 = *(const float4*)(hrow + tx * 4);
        float4 h1 = *(const float4*)(hrow + 64 + tx * 4);
        float2 a01 = *(float2*)&acc2[i][0];
        float2 a23 = *(float2*)&acc2[i][1];
        float2 a45 = *(float2*)&acc2[i][2];
        float2 a67 = *(float2*)&acc2[i][3];
        float4 o0, o1;
        o0.x = gelu_exact(a01.x + b0.x + h0.x);
        o0.y = gelu_exact(a01.y + b0.y + h0.y);
        o0.z = gelu_exact(a23.x + b0.z + h0.z);
        o0.w = gelu_exact(a23.y + b0.w + h0.w);
        o1.x = gelu_exact(a45.x + b1.x + h1.x);
        o1.y = gelu_exact(a45.y + b1.y + h1.y);
        o1.z = gelu_exact(a67.x + b1.z + h1.z);
        o1.w = gelu_exact(a67.y + b1.w + h1.w);
        *(float4*)(out + (size_t)row * 128 + tx * 4) = o0;
        *(float4*)(out + (size_t)row * 128 + 64 + tx * 4) = o1;
    }
}

extern "C" void kernel_launch(void* const* d_in, const int* in_sizes, int n_in,
                              void* d_out, int out_size) {
    const float* features = (const float*)d_in[0];
    const int*   src      = (const int*)d_in[1];
    const int*   dst      = (const int*)d_in[2];
    const float* gamma    = (const float*)d_in[3];
    const float* beta     = (const float*)d_in[4];
    const float* Wself    = (const float*)d_in[5];
    const float* Wneigh   = (const float*)d_in[6];
    const float* bias     = (const float*)d_in[7];
    float* out = (float*)d_out;

    int n = in_sizes[0] / DD;
    int e = in_sizes[1];
    int rpb = (n + NPART - 1) / NPART;
    int nblk = (n + 511) / 512;       // <= 256 for NMAX

    // CSR build chain (independent of BN)
    zero_cnt<<<(n + 1023) / 1024, 1024>>>(n);
    hist<<<(e + 255) / 256, 256>>>(dst, e);

    // BN stats
    bn_partial<<<NPART, DD>>>(features, n, rpb);
    bn_finalize<<<1, DD>>>(gamma, beta, n);

    scan1<<<nblk, 512>>>(n);
    scan2<<<1, 256>>>(nblk, n, e);
    scan3<<<nblk, 512>>>(n);
    fill_csr<<<(e + 255) / 256, 256>>>(src, dst, e);

    int slots = n * (DD / 4);
    normalize_h<<<(slots + 255) / 256, 256>>>(features, n);

    aggregate<<<(n * 32 + 255) / 256, 256>>>(n);

    gemm_gelu<<<(n + 127) / 128, 256>>>(Wself, Wneigh, bias, out, n);
}

// round 8
// speedup vs baseline: 1.9436x; 1.1287x over previous
#include <cuda_runtime.h>
#include <math.h>

#define DD 128
#define NMAX 100000
#define EMAX 800000
#define NPART 250

// Scratch (allocation-free: __device__ globals; zero-initialized at load)
__device__ float g_agg[(size_t)NMAX * DD];   // affine-normalized neighbor MEAN
__device__ float g_psum[NPART * DD];
__device__ float g_psq[NPART * DD];
__device__ float g_scale[DD];
__device__ float g_shift[DD];

// CSR scratch
__device__ int g_cnt[NMAX];       // zeroed by scan3 each call (invariant)
__device__ int g_offs[NMAX + 1];
__device__ int g_curs[NMAX];
__device__ int g_part[256];
__device__ int g_csr[EMAX];

__device__ __forceinline__ float gelu_exact(float x) {
    return 0.5f * x * (1.0f + erff(x * 0.70710678118654752440f));
}

// ============ K1: bn_partial (blocks [0,NPART)) ∥ hist (rest) ============
__global__ __launch_bounds__(256) void k_bnpart_hist(
    const float* __restrict__ f, const int* __restrict__ dst,
    int n, int e, int rpb)
{
    __shared__ float ss[256], qq[256];
    int tid = threadIdx.x;
    if (blockIdx.x < NPART) {
        int b = blockIdx.x;
        int d = tid & 127, h2 = tid >> 7;
        int r0 = b * rpb, r1 = min(r0 + rpb, n);
        float s = 0.f, sq = 0.f;
        for (int r = r0 + h2; r < r1; r += 2) {
            float v = f[(size_t)r * DD + d];
            s += v;
            sq += v * v;
        }
        ss[tid] = s; qq[tid] = sq;
        __syncthreads();
        if (h2 == 0) {
            g_psum[b * DD + d] = s + ss[tid + 128];
            g_psq[b * DD + d]  = sq + qq[tid + 128];
        }
    } else {
        int t = (blockIdx.x - NPART) * 256 + tid;
        if (t < e) atomicAdd(&g_cnt[dst[t]], 1);
    }
}

// ============ K2: scan1 (blocks [0,nblk)) ∥ bn_finalize (128 blocks) =====
__global__ __launch_bounds__(512) void k_scan1_bnfin(
    const float* __restrict__ gamma, const float* __restrict__ beta,
    int n, int nblk)
{
    __shared__ int sm[512];
    __shared__ float rs[512], rq[512];
    int t = threadIdx.x;
    if (blockIdx.x < nblk) {
        // per-block local exclusive scan of g_cnt -> g_offs; totals -> g_part
        int i = blockIdx.x * 512 + t;
        int v = (i < n) ? g_cnt[i] : 0;
        sm[t] = v;
        __syncthreads();
        #pragma unroll
        for (int d = 1; d < 512; d <<= 1) {
            int x = (t >= d) ? sm[t - d] : 0;
            __syncthreads();
            sm[t] += x;
            __syncthreads();
        }
        if (i < n) g_offs[i] = sm[t] - v;
        if (t == 511) g_part[blockIdx.x] = sm[511];
    } else {
        // bn_finalize: one block per feature dim, tree-reduce 250 partials
        int d = blockIdx.x - nblk;
        float s = 0.f, sq = 0.f;
        if (t < NPART) {
            s  = g_psum[t * DD + d];
            sq = g_psq[t * DD + d];
        }
        rs[t] = s; rq[t] = sq;
        __syncthreads();
        #pragma unroll
        for (int off = 256; off > 0; off >>= 1) {
            if (t < off) { rs[t] += rs[t + off]; rq[t] += rq[t + off]; }
            __syncthreads();
        }
        if (t == 0) {
            float inv_n = 1.0f / (float)n;
            float mean = rs[0] * inv_n;
            float var  = rq[0] * inv_n - mean * mean;
            float rstd = rsqrtf(var + 1e-5f);
            float sc = gamma[d] * rstd;
            g_scale[d] = sc;
            g_shift[d] = beta[d] - mean * sc;
        }
    }
}

// ============ K3: scan2 (block totals, nblk <= 256) ======================
__global__ void scan2(int nblk, int n, int e) {
    __shared__ int sm[256];
    int t = threadIdx.x;
    int v = (t < nblk) ? g_part[t] : 0;
    sm[t] = v;
    __syncthreads();
    #pragma unroll
    for (int d = 1; d < 256; d <<= 1) {
        int x = (t >= d) ? sm[t - d] : 0;
        __syncthreads();
        sm[t] += x;
        __syncthreads();
    }
    if (t < nblk) g_part[t] = sm[t] - v;
    if (t == 0) g_offs[n] = e;
}

// ============ K4: scan3 (finalize offsets, init cursor, re-zero cnt) =====
__global__ void scan3(int n) {
    int i = blockIdx.x * 512 + threadIdx.x;
    if (i < n) {
        int o = g_offs[i] + g_part[blockIdx.x];
        g_offs[i] = o;
        g_curs[i] = o;
        g_cnt[i]  = 0;            // restore invariant for next call
    }
}

// ============ K5: fill CSR ==============================================
__global__ void fill_csr(const int* __restrict__ src,
                         const int* __restrict__ dst, int e) {
    int t = blockIdx.x * blockDim.x + threadIdx.x;
    if (t >= e) return;
    int pos = atomicAdd(&g_curs[dst[t]], 1);
    g_csr[pos] = src[t];
}

// ============ K6: aggregate (warp/node, raw gather, affine at write) =====
__global__ void aggregate(const float* __restrict__ f, int n) {
    int w = (blockIdx.x * blockDim.x + threadIdx.x) >> 5;
    int lane = threadIdx.x & 31;
    if (w >= n) return;
    int i  = g_offs[w];
    int s1 = g_offs[w + 1];
    int deg = s1 - i;
    float4 acc = make_float4(0.f, 0.f, 0.f, 0.f);
    int nexts = (i < s1) ? g_csr[i] : 0;
    while (i < s1) {
        int s = nexts;
        ++i;
        if (i < s1) nexts = g_csr[i];          // prefetch next index
        float4 v = ((const float4*)(f + (size_t)s * DD))[lane];
        acc.x += v.x; acc.y += v.y; acc.z += v.z; acc.w += v.w;
    }
    float4 r = make_float4(0.f, 0.f, 0.f, 0.f);
    if (deg > 0) {
        // mean of (f*sc+sh) == sc * mean(f) + sh
        float inv = 1.0f / (float)deg;
        float4 sc = ((const float4*)g_scale)[lane];
        float4 sh = ((const float4*)g_shift)[lane];
        r.x = fmaf(acc.x * inv, sc.x, sh.x);
        r.y = fmaf(acc.y * inv, sc.y, sh.y);
        r.z = fmaf(acc.z * inv, sc.z, sh.z);
        r.w = fmaf(acc.w * inv, sc.w, sh.w);
    }
    ((float4*)(g_agg + (size_t)w * DD))[lane] = r;
}

// ============ K7: fused GEMM + affine-A + bias + skip + GELU =============
// conv = [h | hn] @ [W_self ; W_neigh]  (M x 256) @ (256 x 128)
// h is computed on the fly from raw features (affine in the A-tile load).
__global__ __launch_bounds__(256) void gemm_gelu(
    const float* __restrict__ f,
    const float* __restrict__ Wself, const float* __restrict__ Wneigh,
    const float* __restrict__ bias, float* __restrict__ out, int n)
{
    __shared__ float As[16][128];   // [k][row]
    __shared__ float Bs[16][128];   // [k][col]

    int tid = threadIdx.x;
    int tx = tid & 15;
    int ty = tid >> 4;
    int rowBase = blockIdx.x * 128;

    unsigned long long acc2[8][4];
    #pragma unroll
    for (int i = 0; i < 8; ++i)
        #pragma unroll
        for (int j = 0; j < 4; ++j) acc2[i][j] = 0ull;

    for (int k0 = 0; k0 < 256; k0 += 16) {
        bool firstHalf = (k0 < 128);
        const float* Bsrc = firstHalf ? (Wself + (size_t)k0 * 128)
                                      : (Wneigh + (size_t)(k0 - 128) * 128);
        #pragma unroll
        for (int r = 0; r < 2; ++r) {
            int s = tid + r * 256;
            int row = s >> 2, kq = s & 3;
            int grow = rowBase + row;
            float4 v = make_float4(0.f, 0.f, 0.f, 0.f);
            if (grow < n) {
                if (firstHalf) {
                    int kc = k0 + kq * 4;
                    float4 v0 = *(const float4*)(f + (size_t)grow * DD + kc);
                    float4 sc = *(const float4*)(g_scale + kc);
                    float4 sh = *(const float4*)(g_shift + kc);
                    v.x = fmaf(v0.x, sc.x, sh.x);
                    v.y = fmaf(v0.y, sc.y, sh.y);
                    v.z = fmaf(v0.z, sc.z, sh.z);
                    v.w = fmaf(v0.w, sc.w, sh.w);
                } else {
                    v = *(const float4*)(g_agg + (size_t)grow * DD +
                                         (k0 - 128) + kq * 4);
                }
            }
            As[kq * 4 + 0][row] = v.x;
            As[kq * 4 + 1][row] = v.y;
            As[kq * 4 + 2][row] = v.z;
            As[kq * 4 + 3][row] = v.w;
        }
        #pragma unroll
        for (int r = 0; r < 2; ++r) {
            int s = tid + r * 256;
            int kk = s >> 5, n4 = s & 31;
            float4 v = *(const float4*)(Bsrc + kk * 128 + n4 * 4);
            *(float4*)&Bs[kk][n4 * 4] = v;
        }
        __syncthreads();

        #pragma unroll
        for (int k = 0; k < 16; ++k) {
            float a[8];
            *(float4*)&a[0] = *(const float4*)&As[k][ty * 8];
            *(float4*)&a[4] = *(const float4*)&As[k][ty * 8 + 4];
            ulonglong2 bp0 = *(const ulonglong2*)&Bs[k][tx * 4];
            ulonglong2 bp1 = *(const ulonglong2*)&Bs[k][64 + tx * 4];
            unsigned long long b2[4];
            b2[0] = bp0.x; b2[1] = bp0.y; b2[2] = bp1.x; b2[3] = bp1.y;
            #pragma unroll
            for (int i = 0; i < 8; ++i) {
                unsigned long long a2;
                asm("mov.b64 %0, {%1, %1};" : "=l"(a2) : "f"(a[i]));
                #pragma unroll
                for (int j = 0; j < 4; ++j) {
                    asm("fma.rn.f32x2 %0, %1, %2, %0;"
                        : "+l"(acc2[i][j]) : "l"(a2), "l"(b2[j]));
                }
            }
        }
        __syncthreads();
    }

    float4 b0 = ((const float4*)bias)[tx];
    float4 b1 = ((const float4*)bias)[16 + tx];
    float4 sc0 = ((const float4*)g_scale)[tx];
    float4 sh0 = ((const float4*)g_shift)[tx];
    float4 sc1 = ((const float4*)g_scale)[16 + tx];
    float4 sh1 = ((const float4*)g_shift)[16 + tx];

    #pragma unroll
    for (int i = 0; i < 8; ++i) {
        int row = rowBase + ty * 8 + i;
        if (row >= n) break;
        const float* frow = f + (size_t)row * 128;
        float4 f0 = *(const float4*)(frow + tx * 4);
        float4 f1 = *(const float4*)(frow + 64 + tx * 4);
        float4 h0, h1;
        h0.x = fmaf(f0.x, sc0.x, sh0.x);
        h0.y = fmaf(f0.y, sc0.y, sh0.y);
        h0.z = fmaf(f0.z, sc0.z, sh0.z);
        h0.w = fmaf(f0.w, sc0.w, sh0.w);
        h1.x = fmaf(f1.x, sc1.x, sh1.x);
        h1.y = fmaf(f1.y, sc1.y, sh1.y);
        h1.z = fmaf(f1.z, sc1.z, sh1.z);
        h1.w = fmaf(f1.w, sc1.w, sh1.w);
        float2 a01 = *(float2*)&acc2[i][0];
        float2 a23 = *(float2*)&acc2[i][1];
        float2 a45 = *(float2*)&acc2[i][2];
        float2 a67 = *(float2*)&acc2[i][3];
        float4 o0, o1;
        o0.x = gelu_exact(a01.x + b0.x + h0.x);
        o0.y = gelu_exact(a01.y + b0.y + h0.y);
        o0.z = gelu_exact(a23.x + b0.z + h0.z);
        o0.w = gelu_exact(a23.y + b0.w + h0.w);
        o1.x = gelu_exact(a45.x + b1.x + h1.x);
        o1.y = gelu_exact(a45.y + b1.y + h1.y);
        o1.z = gelu_exact(a67.x + b1.z + h1.z);
        o1.w = gelu_exact(a67.y + b1.w + h1.w);
        *(float4*)(out + (size_t)row * 128 + tx * 4) = o0;
        *(float4*)(out + (size_t)row * 128 + 64 + tx * 4) = o1;
    }
}

extern "C" void kernel_launch(void* const* d_in, const int* in_sizes, int n_in,
                              void* d_out, int out_size) {
    const float* features = (const float*)d_in[0];
    const int*   src      = (const int*)d_in[1];
    const int*   dst      = (const int*)d_in[2];
    const float* gamma    = (const float*)d_in[3];
    const float* beta     = (const float*)d_in[4];
    const float* Wself    = (const float*)d_in[5];
    const float* Wneigh   = (const float*)d_in[6];
    const float* bias     = (const float*)d_in[7];
    float* out = (float*)d_out;

    int n = in_sizes[0] / DD;
    int e = in_sizes[1];
    int rpb = (n + NPART - 1) / NPART;
    int nblk = (n + 511) / 512;                // <= 196 for NMAX
    int histBlocks = (e + 255) / 256;

    // K1: BN partial stats ∥ degree histogram (g_cnt is zero by invariant)
    k_bnpart_hist<<<NPART + histBlocks, 256>>>(features, dst, n, e, rpb);

    // K2: local scan of degrees ∥ BN finalize (scale/shift)
    k_scan1_bnfin<<<nblk + DD, 512>>>(gamma, beta, n, nblk);

    // K3-K5: finish CSR build
    scan2<<<1, 256>>>(nblk, n, e);
    scan3<<<nblk, 512>>>(n);
    fill_csr<<<histBlocks, 256>>>(src, dst, e);

    // K6: neighbor mean (affine folded in)
    aggregate<<<(n * 32 + 255) / 256, 256>>>(features, n);

    // K7: fused GEMM + bias + skip + GELU
    gemm_gelu<<<(n + 127) / 128, 256>>>(features, Wself, Wneigh, bias, out, n);
}

// round 9
// speedup vs baseline: 1.9545x; 1.0056x over previous
#include <cuda_runtime.h>
#include <math.h>

#define DD 128
#define NMAX 100000
#define EMAX 800000
#define NPART 250

// Scratch (allocation-free: __device__ globals; zero-initialized at load)
__device__ float g_agg[(size_t)NMAX * DD];   // affine-normalized neighbor MEAN
__device__ float g_psum[NPART * DD];
__device__ float g_psq[NPART * DD];
__device__ float g_scale[DD];
__device__ float g_shift[DD];

// CSR scratch
__device__ int g_cnt[NMAX];       // zeroed by scan3 each call (invariant)
__device__ int g_offs[NMAX + 1];
__device__ int g_curs[NMAX];
__device__ int g_part[256];
__device__ int g_csr[EMAX];

__device__ __forceinline__ float gelu_exact(float x) {
    return 0.5f * x * (1.0f + erff(x * 0.70710678118654752440f));
}

// ============ K1: bn_partial (blocks [0,NPART)) ∥ hist (rest) ============
__global__ __launch_bounds__(256) void k_bnpart_hist(
    const float* __restrict__ f, const int* __restrict__ dst,
    int n, int e, int rpb)
{
    __shared__ float ss[256], qq[256];
    int tid = threadIdx.x;
    if (blockIdx.x < NPART) {
        int b = blockIdx.x;
        int d = tid & 127, h2 = tid >> 7;
        int r0 = b * rpb, r1 = min(r0 + rpb, n);
        float s = 0.f, sq = 0.f;
        for (int r = r0 + h2; r < r1; r += 2) {
            float v = f[(size_t)r * DD + d];
            s += v;
            sq += v * v;
        }
        ss[tid] = s; qq[tid] = sq;
        __syncthreads();
        if (h2 == 0) {
            g_psum[b * DD + d] = s + ss[tid + 128];
            g_psq[b * DD + d]  = sq + qq[tid + 128];
        }
    } else {
        int t = (blockIdx.x - NPART) * 256 + tid;
        if (t < e) atomicAdd(&g_cnt[dst[t]], 1);
    }
}

// ============ K2: scan1 (blocks [0,nblk)) ∥ bn_finalize (128 blocks) =====
__global__ __launch_bounds__(512) void k_scan1_bnfin(
    const float* __restrict__ gamma, const float* __restrict__ beta,
    int n, int nblk)
{
    __shared__ int sm[512];
    __shared__ float rs[512], rq[512];
    int t = threadIdx.x;
    if (blockIdx.x < nblk) {
        // per-block local exclusive scan of g_cnt -> g_offs; totals -> g_part
        int i = blockIdx.x * 512 + t;
        int v = (i < n) ? g_cnt[i] : 0;
        sm[t] = v;
        __syncthreads();
        #pragma unroll
        for (int d = 1; d < 512; d <<= 1) {
            int x = (t >= d) ? sm[t - d] : 0;
            __syncthreads();
            sm[t] += x;
            __syncthreads();
        }
        if (i < n) g_offs[i] = sm[t] - v;
        if (t == 511) g_part[blockIdx.x] = sm[511];
    } else {
        // bn_finalize: one block per feature dim, tree-reduce 250 partials
        int d = blockIdx.x - nblk;
        float s = 0.f, sq = 0.f;
        if (t < NPART) {
            s  = g_psum[t * DD + d];
            sq = g_psq[t * DD + d];
        }
        rs[t] = s; rq[t] = sq;
        __syncthreads();
        #pragma unroll
        for (int off = 256; off > 0; off >>= 1) {
            if (t < off) { rs[t] += rs[t + off]; rq[t] += rq[t + off]; }
            __syncthreads();
        }
        if (t == 0) {
            float inv_n = 1.0f / (float)n;
            float mean = rs[0] * inv_n;
            float var  = rq[0] * inv_n - mean * mean;
            float rstd = rsqrtf(var + 1e-5f);
            float sc = gamma[d] * rstd;
            g_scale[d] = sc;
            g_shift[d] = beta[d] - mean * sc;
        }
    }
}

// ============ K3: scan2 (block totals, nblk <= 256) ======================
__global__ void scan2(int nblk, int n, int e) {
    __shared__ int sm[256];
    int t = threadIdx.x;
    int v = (t < nblk) ? g_part[t] : 0;
    sm[t] = v;
    __syncthreads();
    #pragma unroll
    for (int d = 1; d < 256; d <<= 1) {
        int x = (t >= d) ? sm[t - d] : 0;
        __syncthreads();
        sm[t] += x;
        __syncthreads();
    }
    if (t < nblk) g_part[t] = sm[t] - v;
    if (t == 0) g_offs[n] = e;
}

// ============ K4: scan3 (finalize offsets, init cursor, re-zero cnt) =====
__global__ void scan3(int n) {
    int i = blockIdx.x * 512 + threadIdx.x;
    if (i < n) {
        int o = g_offs[i] + g_part[blockIdx.x];
        g_offs[i] = o;
        g_curs[i] = o;
        g_cnt[i]  = 0;            // restore invariant for next call
    }
}

// ============ K5: fill CSR ==============================================
__global__ void fill_csr(const int* __restrict__ src,
                         const int* __restrict__ dst, int e) {
    int t = blockIdx.x * blockDim.x + threadIdx.x;
    if (t >= e) return;
    int pos = atomicAdd(&g_curs[dst[t]], 1);
    g_csr[pos] = src[t];
}

// ============ K6: aggregate (warp/node, raw gather, affine at write) =====
__global__ void aggregate(const float* __restrict__ f, int n) {
    int w = (blockIdx.x * blockDim.x + threadIdx.x) >> 5;
    int lane = threadIdx.x & 31;
    if (w >= n) return;
    int i  = g_offs[w];
    int s1 = g_offs[w + 1];
    int deg = s1 - i;
    float4 acc = make_float4(0.f, 0.f, 0.f, 0.f);
    int nexts = (i < s1) ? g_csr[i] : 0;
    while (i < s1) {
        int s = nexts;
        ++i;
        if (i < s1) nexts = g_csr[i];          // prefetch next index
        float4 v = ((const float4*)(f + (size_t)s * DD))[lane];
        acc.x += v.x; acc.y += v.y; acc.z += v.z; acc.w += v.w;
    }
    float4 r = make_float4(0.f, 0.f, 0.f, 0.f);
    if (deg > 0) {
        // mean of (f*sc+sh) == sc * mean(f) + sh
        float inv = 1.0f / (float)deg;
        float4 sc = ((const float4*)g_scale)[lane];
        float4 sh = ((const float4*)g_shift)[lane];
        r.x = fmaf(acc.x * inv, sc.x, sh.x);
        r.y = fmaf(acc.y * inv, sc.y, sh.y);
        r.z = fmaf(acc.z * inv, sc.z, sh.z);
        r.w = fmaf(acc.w * inv, sc.w, sh.w);
    }
    ((float4*)(g_agg + (size_t)w * DD))[lane] = r;
}

// ============ K7: fused GEMM + affine-A + bias + skip + GELU =============
// conv = [h | hn] @ [W_self ; W_neigh]  (M x 256) @ (256 x 128)
// h is computed on the fly from raw features (affine in the A-tile load).
__global__ __launch_bounds__(256) void gemm_gelu(
    const float* __restrict__ f,
    const float* __restrict__ Wself, const float* __restrict__ Wneigh,
    const float* __restrict__ bias, float* __restrict__ out, int n)
{
    __shared__ float As[16][128];   // [k][row]
    __shared__ float Bs[16][128];   // [k][col]

    int tid = threadIdx.x;
    int tx = tid & 15;
    int ty = tid >> 4;
    int rowBase = blockIdx.x * 128;

    unsigned long long acc2[8][4];
    #pragma unroll
    for (int i = 0; i < 8; ++i)
        #pragma unroll
        for (int j = 0; j < 4; ++j) acc2[i][j] = 0ull;

    for (int k0 = 0; k0 < 256; k0 += 16) {
        bool firstHalf = (k0 < 128);
        const float* Bsrc = firstHalf ? (Wself + (size_t)k0 * 128)
                                      : (Wneigh + (size_t)(k0 - 128) * 128);
        #pragma unroll
        for (int r = 0; r < 2; ++r) {
            int s = tid + r * 256;
            int row = s >> 2, kq = s & 3;
            int grow = rowBase + row;
            float4 v = make_float4(0.f, 0.f, 0.f, 0.f);
            if (grow < n) {
                if (firstHalf) {
                    int kc = k0 + kq * 4;
                    float4 v0 = *(const float4*)(f + (size_t)grow * DD + kc);
                    float4 sc = *(const float4*)(g_scale + kc);
                    float4 sh = *(const float4*)(g_shift + kc);
                    v.x = fmaf(v0.x, sc.x, sh.x);
                    v.y = fmaf(v0.y, sc.y, sh.y);
                    v.z = fmaf(v0.z, sc.z, sh.z);
                    v.w = fmaf(v0.w, sc.w, sh.w);
                } else {
                    v = *(const float4*)(g_agg + (size_t)grow * DD +
                                         (k0 - 128) + kq * 4);
                }
            }
            As[kq * 4 + 0][row] = v.x;
            As[kq * 4 + 1][row] = v.y;
            As[kq * 4 + 2][row] = v.z;
            As[kq * 4 + 3][row] = v.w;
        }
        #pragma unroll
        for (int r = 0; r < 2; ++r) {
            int s = tid + r * 256;
            int kk = s >> 5, n4 = s & 31;
            float4 v = *(const float4*)(Bsrc + kk * 128 + n4 * 4);
            *(float4*)&Bs[kk][n4 * 4] = v;
        }
        __syncthreads();

        #pragma unroll
        for (int k = 0; k < 16; ++k) {
            float a[8];
            *(float4*)&a[0] = *(const float4*)&As[k][ty * 8];
            *(float4*)&a[4] = *(const float4*)&As[k][ty * 8 + 4];
            ulonglong2 bp0 = *(const ulonglong2*)&Bs[k][tx * 4];
            ulonglong2 bp1 = *(const ulonglong2*)&Bs[k][64 + tx * 4];
            unsigned long long b2[4];
            b2[0] = bp0.x; b2[1] = bp0.y; b2[2] = bp1.x; b2[3] = bp1.y;
            #pragma unroll
            for (int i = 0; i < 8; ++i) {
                unsigned long long a2;
                asm("mov.b64 %0, {%1, %1};" : "=l"(a2) : "f"(a[i]));
                #pragma unroll
                for (int j = 0; j < 4; ++j) {
                    asm("fma.rn.f32x2 %0, %1, %2, %0;"
                        : "+l"(acc2[i][j]) : "l"(a2), "l"(b2[j]));
                }
            }
        }
        __syncthreads();
    }

    float4 b0 = ((const float4*)bias)[tx];
    float4 b1 = ((const float4*)bias)[16 + tx];
    float4 sc0 = ((const float4*)g_scale)[tx];
    float4 sh0 = ((const float4*)g_shift)[tx];
    float4 sc1 = ((const float4*)g_scale)[16 + tx];
    float4 sh1 = ((const float4*)g_shift)[16 + tx];

    #pragma unroll
    for (int i = 0; i < 8; ++i) {
        int row = rowBase + ty * 8 + i;
        if (row >= n) break;
        const float* frow = f + (size_t)row * 128;
        float4 f0 = *(const float4*)(frow + tx * 4);
        float4 f1 = *(const float4*)(frow + 64 + tx * 4);
        float4 h0, h1;
        h0.x = fmaf(f0.x, sc0.x, sh0.x);
        h0.y = fmaf(f0.y, sc0.y, sh0.y);
        h0.z = fmaf(f0.z, sc0.z, sh0.z);
        h0.w = fmaf(f0.w, sc0.w, sh0.w);
        h1.x = fmaf(f1.x, sc1.x, sh1.x);
        h1.y = fmaf(f1.y, sc1.y, sh1.y);
        h1.z = fmaf(f1.z, sc1.z, sh1.z);
        h1.w = fmaf(f1.w, sc1.w, sh1.w);
        float2 a01 = *(float2*)&acc2[i][0];
        float2 a23 = *(float2*)&acc2[i][1];
        float2 a45 = *(float2*)&acc2[i][2];
        float2 a67 = *(float2*)&acc2[i][3];
        float4 o0, o1;
        o0.x = gelu_exact(a01.x + b0.x + h0.x);
        o0.y = gelu_exact(a01.y + b0.y + h0.y);
        o0.z = gelu_exact(a23.x + b0.z + h0.z);
        o0.w = gelu_exact(a23.y + b0.w + h0.w);
        o1.x = gelu_exact(a45.x + b1.x + h1.x);
        o1.y = gelu_exact(a45.y + b1.y + h1.y);
        o1.z = gelu_exact(a67.x + b1.z + h1.z);
        o1.w = gelu_exact(a67.y + b1.w + h1.w);
        *(float4*)(out + (size_t)row * 128 + tx * 4) = o0;
        *(float4*)(out + (size_t)row * 128 + 64 + tx * 4) = o1;
    }
}

extern "C" void kernel_launch(void* const* d_in, const int* in_sizes, int n_in,
                              void* d_out, int out_size) {
    const float* features = (const float*)d_in[0];
    const int*   src      = (const int*)d_in[1];
    const int*   dst      = (const int*)d_in[2];
    const float* gamma    = (const float*)d_in[3];
    const float* beta     = (const float*)d_in[4];
    const float* Wself    = (const float*)d_in[5];
    const float* Wneigh   = (const float*)d_in[6];
    const float* bias     = (const float*)d_in[7];
    float* out = (float*)d_out;

    int n = in_sizes[0] / DD;
    int e = in_sizes[1];
    int rpb = (n + NPART - 1) / NPART;
    int nblk = (n + 511) / 512;                // <= 196 for NMAX
    int histBlocks = (e + 255) / 256;

    // K1: BN partial stats ∥ degree histogram (g_cnt is zero by invariant)
    k_bnpart_hist<<<NPART + histBlocks, 256>>>(features, dst, n, e, rpb);

    // K2: local scan of degrees ∥ BN finalize (scale/shift)
    k_scan1_bnfin<<<nblk + DD, 512>>>(gamma, beta, n, nblk);

    // K3-K5: finish CSR build
    scan2<<<1, 256>>>(nblk, n, e);
    scan3<<<nblk, 512>>>(n);
    fill_csr<<<histBlocks, 256>>>(src, dst, e);

    // K6: neighbor mean (affine folded in)
    aggregate<<<(n * 32 + 255) / 256, 256>>>(features, n);

    // K7: fused GEMM + bias + skip + GELU
    gemm_gelu<<<(n + 127) / 128, 256>>>(features, Wself, Wneigh, bias, out, n);
}